// round 14
// baseline (speedup 1.0000x reference)
#include <cuda_runtime.h>

// PlaneValidator: symmetric-chamfer + per-batch conf ranking + angular NMS.
// Single fused kernel.
//
//  - D[n,m] = |p_n - r_m|^2 SYMMETRIC -> sde = 2 * mean_n min_m D.
//  - row-min of D = p2 + min_m (R2[m] - 2 p.r_m).
//  - 256 blocks x 256 thr, 2 CTAs/SM: 4 warps/SMSP AND 4 rows/thread AND
//    point-pair f32x2 (2 LDS.128 + 12 FFMA2 + 8 FMNMX per 2 cols x 4 rows).
//    Each block: one 256-column quarter x all 1024 rows.
//  - per-bh 4-arrival min-combine, then 64-arrival warp-parallel finalize.

#define NB 4
#define NPTS 1024
#define NH 16
#define THREADS 256
#define ROWS 4                  // rows per thread
#define QCOLS 256               // columns per block (quarter)
#define NBLOCKS (NB * NH * 4)   // 256

#define COS_THR 0.8660254037844387f
#define FULL 0xFFFFFFFFu
#define FINF 3.4e38f

__device__ float g_rowmin[NBLOCKS * NPTS];  // per-block partial row minima (+p2)
__device__ float g_part[NB * NH];           // per-bh raw sums of row minima
__device__ int   g_cnt_bh[NB * NH];         // 4-arrival counters (self-resetting)
__device__ int   g_cnt_fin = 0;             // 64-arrival counter (self-resetting)

__device__ __forceinline__ unsigned long long fma2(
        unsigned long long a, unsigned long long b, unsigned long long c) {
    unsigned long long d;
    asm("fma.rn.f32x2 %0, %1, %2, %3;" : "=l"(d) : "l"(a), "l"(b), "l"(c));
    return d;
}
__device__ __forceinline__ unsigned long long pack2(float lo, float hi) {
    unsigned long long d;
    asm("mov.b64 %0, {%1, %2};" : "=l"(d) : "f"(lo), "f"(hi));
    return d;
}
__device__ __forceinline__ void unpack2(unsigned long long v, float& lo, float& hi) {
    asm("mov.b64 {%0, %1}, %2;" : "=f"(lo), "=f"(hi) : "l"(v));
}

__global__ __launch_bounds__(THREADS, 2) void plane_validator_kernel(
        const float* __restrict__ pts, const float* __restrict__ ypred,
        const int* __restrict__ thr_ptr, float* __restrict__ out) {
    const int bid = blockIdx.x;
    const int bh  = bid >> 2;          // (b,h) pair
    const int cq  = bid & 3;           // column quarter
    const int t   = threadIdx.x;

    // ---------------- chamfer phase ----------------
    const float* yp = ypred + bh * 4;
    const float nx = yp[0], ny = yp[1], nz = yp[2], dpl = yp[3];
    const float inv = 1.0f / sqrtf(nx * nx + ny * ny + nz * nz);
    const float nhx = nx * inv, nhy = ny * inv, nhz = nz * inv;
    const float dh  = dpl * inv;

    const float* pb = pts + (bh >> 4) * (NPTS * 3);

    // Point-pair packed column tile (4 KB):
    //   word 2k   = { {-2rx_p0,-2rx_p1}, {-2ry_p0,-2ry_p1} }
    //   word 2k+1 = { {-2rz_p0,-2rz_p1}, { r2_p0 , r2_p1 } }   (p0=2k, p1=2k+1 local)
    __shared__ ulonglong2 sB[QCOLS / 2 * 2];   // QCOLS points, 16B each
    {
        float* sF = (float*)sB;
        int i = t;                              // 256 thr = 256 local points
        int g = cq * QCOLS + i;                 // global point index
        float px = pb[g * 3 + 0], py = pb[g * 3 + 1], pz = pb[g * 3 + 2];
        float proj = fmaf(px, nhx, fmaf(py, nhy, fmaf(pz, nhz, dh)));
        float s = -2.0f * proj;
        float rx = fmaf(s, nhx, px);
        float ry = fmaf(s, nhy, py);
        float rz = fmaf(s, nhz, pz);
        float r2 = fmaf(rx, rx, fmaf(ry, ry, rz * rz));
        int base = (i >> 1) * 8 + (i & 1);
        sF[base + 0] = -2.0f * rx;
        sF[base + 2] = -2.0f * ry;
        sF[base + 4] = -2.0f * rz;
        sF[base + 6] = r2;
    }

    // This thread's 4 rows (plain points): coords broadcast into both f32x2 lanes
    float p2[ROWS];
    unsigned long long ax2[ROWS], ay2[ROWS], az2[ROWS];
#pragma unroll
    for (int k = 0; k < ROWS; k++) {
        int r = k * THREADS + t;
        float px = pb[r * 3 + 0], py = pb[r * 3 + 1], pz = pb[r * 3 + 2];
        ax2[k] = pack2(px, px);
        ay2[k] = pack2(py, py);
        az2[k] = pack2(pz, pz);
        p2[k] = fmaf(px, px, fmaf(py, py, pz * pz));
    }
    __syncthreads();

    // e_{p0,p1} = {R2 - 2 p.r} for 2 cols x 4 rows per body; 8 min chains.
    float bLo[ROWS], bHi[ROWS];
#pragma unroll
    for (int k = 0; k < ROWS; k++) { bLo[k] = FINF; bHi[k] = FINF; }

#pragma unroll 4
    for (int m = 0; m < QCOLS / 2; m++) {
        ulonglong2 u0 = sB[2 * m];       // {xx, yy}
        ulonglong2 u1 = sB[2 * m + 1];   // {zz, rr}
#pragma unroll
        for (int k = 0; k < ROWS; k++) {
            unsigned long long e = fma2(ax2[k], u0.x,
                                   fma2(ay2[k], u0.y,
                                   fma2(az2[k], u1.x, u1.y)));
            float elo, ehi;
            unpack2(e, elo, ehi);
            bLo[k] = fminf(bLo[k], elo);
            bHi[k] = fminf(bHi[k], ehi);
        }
    }

    // min(e)+p2 = min(e+p2): safe to min-combine across quarters later.
    float v[ROWS];
#pragma unroll
    for (int k = 0; k < ROWS; k++) {
        v[k] = fminf(bLo[k], bHi[k]) + p2[k];
        g_rowmin[bid * NPTS + k * THREADS + t] = v[k];
    }
    __threadfence();            // each thread publishes its own stores
    __syncthreads();            // all fences done before arrival

    __shared__ int s_flag;
    if (t == 0) {
        int old = atomicAdd(&g_cnt_bh[bh], 1);
        s_flag = (old == 3);    // fourth arriver combines
    }
    __syncthreads();
    if (!s_flag) return;

    // ---------------- combine phase (one block per bh) ----------------
    __threadfence();            // acquire peers' published rowmins
    const int base = bid & ~3;
    volatile float* rm = g_rowmin;
    float s = 0.0f;
#pragma unroll
    for (int k = 0; k < ROWS; k++) {
        float mv = v[k];
#pragma unroll
        for (int q = 0; q < 4; q++) {
            int pb2 = base + q;
            if (pb2 != bid) mv = fminf(mv, rm[pb2 * NPTS + k * THREADS + t]);
        }
        s += mv;
    }

#pragma unroll
    for (int o = 16; o > 0; o >>= 1)
        s += __shfl_down_sync(FULL, s, o);

    __shared__ float wsum[THREADS / 32];
    if ((t & 31) == 0) wsum[t >> 5] = s;
    __syncthreads();
    if (t == 0) {
        float tot = 0.0f;
#pragma unroll
        for (int i = 0; i < THREADS / 32; i++) tot += wsum[i];
        g_part[bh] = tot;            // raw sum of 1024 row-mins
        g_cnt_bh[bh] = 0;            // reset group counter for next replay
        __threadfence();
        int old2 = atomicAdd(&g_cnt_fin, 1);
        s_flag = (old2 == NB * NH - 1);
        if (old2 == NB * NH - 1) g_cnt_fin = 0;   // reset for next replay
    }
    __syncthreads();
    if (!s_flag) return;

    // ---------------- finalize phase (last combiner; lanes 0..63) ----------------
    __shared__ float s_ex[8][64];   // exchange: nx,ny,nz,px,py,pz,cf,sd by sorted pos

    const int l = t;
    float v_nx = 0, v_ny = 0, v_nz = 0, v_px = 0, v_py = 0, v_pz = 0, v_cf = 0, v_sd = 0;
    int pos = l & 15, b = l >> 4;

    if (l < 64) {
        // threshold: decode int32 vs float32 bit pattern defensively
        int tv = thr_ptr[0];
        float tf = __int_as_float(tv);
        float thr = (tf >= 1e-6f && tf <= 1e9f) ? tf : (float)tv;

        const float* yq = ypred + l * 4;
        float qx = yq[0], qy = yq[1], qz = yq[2], qd = yq[3];
        float qi = 1.0f / sqrtf(qx * qx + qy * qy + qz * qz);
        v_nx = qx * qi; v_ny = qy * qi; v_nz = qz * qi;
        float qdh = qd * qi;
        v_px = -qdh * v_nx; v_py = -qdh * v_ny; v_pz = -qdh * v_nz;

        // sde = 2 * mean(row mins)   (D symmetric)
        volatile float* gp = g_part;
        v_sd = gp[l] * (2.0f / (float)NPTS);

        // group min/max over 16 lanes
        float mn = v_sd, mx = v_sd;
#pragma unroll
        for (int o = 8; o > 0; o >>= 1) {
            mn = fminf(mn, __shfl_xor_sync(FULL, mn, o, 16));
            mx = fmaxf(mx, __shfl_xor_sync(FULL, mx, o, 16));
        }
        v_cf = 1.0f - (v_sd - mn) / (mx - mn);

        // stable descending rank (== stable argsort(-cf))
        int rank = 0;
#pragma unroll
        for (int j = 0; j < NH; j++) {
            float cfj = __shfl_sync(FULL, v_cf, j, 16);
            rank += (cfj > v_cf) || (cfj == v_cf && j < pos);
        }
        int slot = b * NH + rank;
        s_ex[0][slot] = v_nx; s_ex[1][slot] = v_ny; s_ex[2][slot] = v_nz;
        s_ex[3][slot] = v_px; s_ex[4][slot] = v_py; s_ex[5][slot] = v_pz;
        s_ex[6][slot] = v_cf; s_ex[7][slot] = v_sd;
        v_cf = thr;  // carry thr across the barrier
    }
    __syncthreads();
    if (l >= 64) return;

    float thr = v_cf;
    v_nx = s_ex[0][l]; v_ny = s_ex[1][l]; v_nz = s_ex[2][l];
    v_px = s_ex[3][l]; v_py = s_ex[4][l]; v_pz = s_ex[5][l];
    v_cf = s_ex[6][l]; v_sd = s_ex[7][l];

    // sequential NMS over sorted positions, live keep bits
    int keep = (v_sd <= thr);
#pragma unroll
    for (int i = 0; i < NH; i++) {
        int   ki  = __shfl_sync(FULL, keep, i, 16);
        float inx = __shfl_sync(FULL, v_nx, i, 16);
        float iny = __shfl_sync(FULL, v_ny, i, 16);
        float inz = __shfl_sync(FULL, v_nz, i, 16);
        float dt = inx * v_nx + iny * v_ny + inz * v_nz;
        if (ki && pos > i && dt > COS_THR) keep = 0;
    }

    // stable partition destination: kept first (in order), dropped after (in order)
    unsigned ball = __ballot_sync(FULL, keep);
    unsigned seg = (ball >> (l & 16)) & 0xFFFFu;
    int kept_before = __popc(seg & ((1u << pos) - 1));
    int total_kept  = __popc(seg);
    int dest = keep ? kept_before : total_kept + (pos - kept_before);

    float* o = out + (b * NH + dest) * 8;
    float4 r0 = keep ? make_float4(v_nx, v_ny, v_nz, v_px) : make_float4(0, 0, 0, 0);
    float4 r1 = keep ? make_float4(v_py, v_pz, v_cf, v_sd) : make_float4(0, 0, 0, 0);
    ((float4*)o)[0] = r0;
    ((float4*)o)[1] = r1;
}

extern "C" void kernel_launch(void* const* d_in, const int* in_sizes, int n_in,
                              void* d_out, int out_size) {
    const float* pts = nullptr;    // 12288 elems
    const float* ypred = nullptr;  // 256 elems
    const int* thr = nullptr;      // 1 elem
    for (int i = 0; i < n_in; i++) {
        if (in_sizes[i] == NB * NPTS * 3)    pts   = (const float*)d_in[i];
        else if (in_sizes[i] == NB * NH * 4) ypred = (const float*)d_in[i];
        else if (in_sizes[i] == 1)           thr   = (const int*)d_in[i];
    }
    float* out = (float*)d_out;

    plane_validator_kernel<<<NBLOCKS, THREADS>>>(pts, ypred, thr, out);
}

// round 15
// speedup vs baseline: 1.0185x; 1.0185x over previous
#include <cuda_runtime.h>

// PlaneValidator: symmetric-chamfer + per-batch conf ranking + angular NMS.
// TWO kernels: chamfer (no inter-block sync machinery at all) + tiny
// warp-parallel finalize.  Stream order replaces fences/atomics/counters.
//
//  - D[n,m] = |p_n - r_m|^2 SYMMETRIC -> sde = 2 * mean_n min_m D.
//  - row-min of D = p2 + min_m (R2[m] - 2 p.r_m): 3 FFMA + 1 FMNMX per pair.
//  - chamfer: 128 blocks x 256 thr, 2 rows/thread, full 1024-col tile,
//    unroll 16, dual min accumulators; block sum -> plain g_part[bid] store.

#define NB 4
#define NPTS 1024
#define NH 16
#define THREADS 256
#define ROW_CHUNK 512           // 2 chunks per (b,h); 2 rows per thread
#define NBLOCKS (NB * NH * 2)   // 128

#define COS_THR 0.8660254037844387f
#define FULL 0xFFFFFFFFu
#define FINF 3.4e38f

__device__ float g_part[NBLOCKS];   // per-block partial sums (rewritten every launch)

__global__ __launch_bounds__(THREADS, 1) void chamfer_kernel(
        const float* __restrict__ pts, const float* __restrict__ ypred) {
    const int bid = blockIdx.x;
    const int bh  = bid >> 1;          // (b,h) pair
    const int rc  = bid & 1;           // row chunk
    const int t   = threadIdx.x;

    const float* yp = ypred + bh * 4;
    const float nx = yp[0], ny = yp[1], nz = yp[2], dpl = yp[3];
    const float inv = 1.0f / sqrtf(nx * nx + ny * ny + nz * nz);
    const float nhx = nx * inv, nhy = ny * inv, nhz = nz * inv;
    const float dh  = dpl * inv;

    const float* pb = pts + (bh >> 4) * (NPTS * 3);

    // Stage columns: reflections as float4(-2rx, -2ry, -2rz, |r|^2)
    __shared__ float4 sB[NPTS];
    for (int i = t; i < NPTS; i += THREADS) {
        float px = pb[i * 3 + 0], py = pb[i * 3 + 1], pz = pb[i * 3 + 2];
        float proj = fmaf(px, nhx, fmaf(py, nhy, fmaf(pz, nhz, dh)));
        float s = -2.0f * proj;
        float rx = fmaf(s, nhx, px);
        float ry = fmaf(s, nhy, py);
        float rz = fmaf(s, nhz, pz);
        float r2 = fmaf(rx, rx, fmaf(ry, ry, rz * rz));
        sB[i] = make_float4(-2.0f * rx, -2.0f * ry, -2.0f * rz, r2);
    }

    // This thread's 2 rows (plain points) + squared norms
    float ax[2], ay[2], az[2], p2[2];
#pragma unroll
    for (int k = 0; k < 2; k++) {
        int r = rc * ROW_CHUNK + k * THREADS + t;
        float px = pb[r * 3 + 0], py = pb[r * 3 + 1], pz = pb[r * 3 + 2];
        ax[k] = px; ay[k] = py; az[k] = pz;
        p2[k] = fmaf(px, px, fmaf(py, py, pz * pz));
    }
    __syncthreads();

    // e_m = R2[m] - 2 p.r_m ; row-min of D = p2 + min e.
    // Dual accumulators per row (even/odd m) shorten the FMNMX chains.
    float b0a = FINF, b0b = FINF, b1a = FINF, b1b = FINF;
#pragma unroll 16
    for (int m = 0; m < NPTS; m += 2) {
        float4 q0 = sB[m];
        float4 q1 = sB[m + 1];
        float e0a = fmaf(ax[0], q0.x, fmaf(ay[0], q0.y, fmaf(az[0], q0.z, q0.w)));
        float e1a = fmaf(ax[1], q0.x, fmaf(ay[1], q0.y, fmaf(az[1], q0.z, q0.w)));
        float e0b = fmaf(ax[0], q1.x, fmaf(ay[0], q1.y, fmaf(az[0], q1.z, q1.w)));
        float e1b = fmaf(ax[1], q1.x, fmaf(ay[1], q1.y, fmaf(az[1], q1.z, q1.w)));
        b0a = fminf(b0a, e0a);
        b1a = fminf(b1a, e1a);
        b0b = fminf(b0b, e0b);
        b1b = fminf(b1b, e1b);
    }
    float acc = (fminf(b0a, b0b) + p2[0]) + (fminf(b1a, b1b) + p2[1]);

#pragma unroll
    for (int o = 16; o > 0; o >>= 1)
        acc += __shfl_down_sync(FULL, acc, o);

    __shared__ float wsum[THREADS / 32];
    if ((t & 31) == 0) wsum[t >> 5] = acc;
    __syncthreads();
    if (t == 0) {
        float s = 0.0f;
#pragma unroll
        for (int i = 0; i < THREADS / 32; i++) s += wsum[i];
        g_part[bid] = s;   // plain store; kernel boundary orders it for finalize
    }
}

// 1 block, 64 threads: lane l = (batch l>>4, plane l&15).
__global__ void finalize_kernel(const float* __restrict__ ypred,
                                const int* __restrict__ thr_ptr,
                                float* __restrict__ out) {
    const int l = threadIdx.x;
    __shared__ float s_ex[8][64];   // exchange by sorted pos

    float v_nx = 0, v_ny = 0, v_nz = 0, v_px = 0, v_py = 0, v_pz = 0, v_cf = 0, v_sd = 0;
    int pos = l & 15, b = l >> 4;
    float thr = 0.0f;

    if (l < 64) {
        // threshold: decode int32 vs float32 bit pattern defensively
        int tv = thr_ptr[0];
        float tf = __int_as_float(tv);
        thr = (tf >= 1e-6f && tf <= 1e9f) ? tf : (float)tv;

        const float* yq = ypred + l * 4;
        float qx = yq[0], qy = yq[1], qz = yq[2], qd = yq[3];
        float qi = 1.0f / sqrtf(qx * qx + qy * qy + qz * qz);
        v_nx = qx * qi; v_ny = qy * qi; v_nz = qz * qi;
        float qdh = qd * qi;
        v_px = -qdh * v_nx; v_py = -qdh * v_ny; v_pz = -qdh * v_nz;

        // sde = 2 * mean(row mins)   (D symmetric)
        v_sd = (g_part[2 * l] + g_part[2 * l + 1]) * (2.0f / (float)NPTS);

        // group min/max over 16 lanes
        float mn = v_sd, mx = v_sd;
#pragma unroll
        for (int o = 8; o > 0; o >>= 1) {
            mn = fminf(mn, __shfl_xor_sync(FULL, mn, o, 16));
            mx = fmaxf(mx, __shfl_xor_sync(FULL, mx, o, 16));
        }
        v_cf = 1.0f - (v_sd - mn) / (mx - mn);

        // stable descending rank (== stable argsort(-cf))
        int rank = 0;
#pragma unroll
        for (int j = 0; j < NH; j++) {
            float cfj = __shfl_sync(FULL, v_cf, j, 16);
            rank += (cfj > v_cf) || (cfj == v_cf && j < pos);
        }
        int slot = b * NH + rank;
        s_ex[0][slot] = v_nx; s_ex[1][slot] = v_ny; s_ex[2][slot] = v_nz;
        s_ex[3][slot] = v_px; s_ex[4][slot] = v_py; s_ex[5][slot] = v_pz;
        s_ex[6][slot] = v_cf; s_ex[7][slot] = v_sd;
    }
    __syncthreads();
    if (l >= 64) return;

    v_nx = s_ex[0][l]; v_ny = s_ex[1][l]; v_nz = s_ex[2][l];
    v_px = s_ex[3][l]; v_py = s_ex[4][l]; v_pz = s_ex[5][l];
    v_cf = s_ex[6][l]; v_sd = s_ex[7][l];

    // sequential NMS over sorted positions, live keep bits
    int keep = (v_sd <= thr);
#pragma unroll
    for (int i = 0; i < NH; i++) {
        int   ki  = __shfl_sync(FULL, keep, i, 16);
        float inx = __shfl_sync(FULL, v_nx, i, 16);
        float iny = __shfl_sync(FULL, v_ny, i, 16);
        float inz = __shfl_sync(FULL, v_nz, i, 16);
        float dt = inx * v_nx + iny * v_ny + inz * v_nz;
        if (ki && pos > i && dt > COS_THR) keep = 0;
    }

    // stable partition destination: kept first (in order), dropped after (in order)
    unsigned ball = __ballot_sync(FULL, keep);
    unsigned seg = (ball >> (l & 16)) & 0xFFFFu;
    int kept_before = __popc(seg & ((1u << pos) - 1));
    int total_kept  = __popc(seg);
    int dest = keep ? kept_before : total_kept + (pos - kept_before);

    float* o = out + (b * NH + dest) * 8;
    float4 r0 = keep ? make_float4(v_nx, v_ny, v_nz, v_px) : make_float4(0, 0, 0, 0);
    float4 r1 = keep ? make_float4(v_py, v_pz, v_cf, v_sd) : make_float4(0, 0, 0, 0);
    ((float4*)o)[0] = r0;
    ((float4*)o)[1] = r1;
}

extern "C" void kernel_launch(void* const* d_in, const int* in_sizes, int n_in,
                              void* d_out, int out_size) {
    const float* pts = nullptr;    // 12288 elems
    const float* ypred = nullptr;  // 256 elems
    const int* thr = nullptr;      // 1 elem
    for (int i = 0; i < n_in; i++) {
        if (in_sizes[i] == NB * NPTS * 3)    pts   = (const float*)d_in[i];
        else if (in_sizes[i] == NB * NH * 4) ypred = (const float*)d_in[i];
        else if (in_sizes[i] == 1)           thr   = (const int*)d_in[i];
    }
    float* out = (float*)d_out;

    chamfer_kernel<<<NBLOCKS, THREADS>>>(pts, ypred);
    finalize_kernel<<<1, 64>>>(ypred, thr, out);
}

// round 16
// speedup vs baseline: 1.1377x; 1.1170x over previous
#include <cuda_runtime.h>

// PlaneValidator: symmetric-chamfer + per-batch conf ranking + angular NMS.
// Single fused kernel, ALGEBRAICALLY RESTRUCTURED:
//
//   D[n,m] = |p_n - r_m|^2 = |p_n - p_m|^2 + 4 s_n s_m,   s_i = p_i.nhat + dhat
//
// The geometry term G = |p_n-p_m|^2 is PLANE-INDEPENDENT: one block computes
// it once per (n,m) and amortizes it over all 16 planes of its batch
// (planes packed pairwise into f32x2 lanes: 1 FFMA2 per h-pair + 1 FMNMX/h).
// sde = 2 * mean_n min_m D  (D symmetric).
//
// Grid: 128 blocks = 4 batches x 32 row-chunks (32 rows each), 256 threads
// = 8 warps, each warp owns a 128-column subset of the full 1024-col tile.
// Column tile: 1024 x 80B records {xyz pad | 8 x packed s-pairs} = 80 KB
// dynamic smem, reused as the cross-warp exchange buffer after the mainloop.
// Tail: last-arriving block (fence+counter) min/sums and runs warp-NMS.

#define NB 4
#define NPTS 1024
#define NH 16
#define THREADS 256
#define NBLOCKS 128             // 4 x 32 row-chunks
#define REC 80                  // bytes per column record
#define SMEM_BYTES (NPTS * REC) // 81920

#define COS_THR 0.8660254037844387f
#define FULL 0xFFFFFFFFu
#define FINF 3.4e38f

__device__ float g_bsum[NBLOCKS * NH];  // per-block, per-plane row-min sums
__device__ int   g_cnt = 0;             // arrival counter (self-resetting)

__device__ __forceinline__ unsigned long long fma2(
        unsigned long long a, unsigned long long b, unsigned long long c) {
    unsigned long long d;
    asm("fma.rn.f32x2 %0, %1, %2, %3;" : "=l"(d) : "l"(a), "l"(b), "l"(c));
    return d;
}
__device__ __forceinline__ unsigned long long pack2(float lo, float hi) {
    unsigned long long d;
    asm("mov.b64 %0, {%1, %2};" : "=l"(d) : "f"(lo), "f"(hi));
    return d;
}
__device__ __forceinline__ void unpack2(unsigned long long v, float& lo, float& hi) {
    asm("mov.b64 {%0, %1}, %2;" : "=f"(lo), "=f"(hi) : "l"(v));
}

__global__ __launch_bounds__(THREADS, 1) void plane_validator_kernel(
        const float* __restrict__ pts, const float* __restrict__ ypred,
        const int* __restrict__ thr_ptr, float* __restrict__ out) {
    extern __shared__ char smem[];
    __shared__ float4 s_pl[NH];         // per-plane {nhx, nhy, nhz, dhat}
    __shared__ int s_last;
    __shared__ float s_ex[8][64];       // finalize exchange

    const int bid  = blockIdx.x;
    const int b    = bid >> 5;          // batch
    const int rc   = bid & 31;          // row chunk (32 rows)
    const int t    = threadIdx.x;
    const int w    = t >> 5;            // warp = column subset
    const int lane = t & 31;

    const float* pb = pts + b * NPTS * 3;

    // Plane parameters (16 planes of this batch)
    if (t < NH) {
        const float* yq = ypred + (b * NH + t) * 4;
        float qx = yq[0], qy = yq[1], qz = yq[2], qd = yq[3];
        float qi = 1.0f / sqrtf(qx * qx + qy * qy + qz * qz);
        s_pl[t] = make_float4(qx * qi, qy * qi, qz * qi, qd * qi);
    }
    __syncthreads();

    // Stage column records: {px,py,pz,0 | 8 x pack2(s_h0, s_h1)}
    for (int i = t; i < NPTS; i += THREADS) {
        float px = pb[3 * i], py = pb[3 * i + 1], pz = pb[3 * i + 2];
        char* rec = smem + i * REC;
        *(float4*)rec = make_float4(px, py, pz, 0.0f);
#pragma unroll
        for (int hp = 0; hp < 8; hp++) {
            float4 p0 = s_pl[2 * hp], p1 = s_pl[2 * hp + 1];
            float s0 = fmaf(px, p0.x, fmaf(py, p0.y, fmaf(pz, p0.z, p0.w)));
            float s1 = fmaf(px, p1.x, fmaf(py, p1.y, fmaf(pz, p1.z, p1.w)));
            *(unsigned long long*)(rec + 16 + 8 * hp) = pack2(s0, s1);
        }
    }

    // Row data: row = rc*32 + lane (same 32 rows for all 8 warps)
    const int row = rc * 32 + lane;
    const float ax = pb[3 * row], ay = pb[3 * row + 1], az = pb[3 * row + 2];
    unsigned long long sn2[8];          // packed {4*s_n^h0, 4*s_n^h1}
#pragma unroll
    for (int hp = 0; hp < 8; hp++) {
        float4 p0 = s_pl[2 * hp], p1 = s_pl[2 * hp + 1];
        float s0 = 4.0f * fmaf(ax, p0.x, fmaf(ay, p0.y, fmaf(az, p0.z, p0.w)));
        float s1 = 4.0f * fmaf(ax, p1.x, fmaf(ay, p1.y, fmaf(az, p1.z, p1.w)));
        sn2[hp] = pack2(s0, s1);
    }
    __syncthreads();

    // Main loop: this warp's 128-column subset, all 16 planes at once.
    float acc[NH];
#pragma unroll
    for (int h = 0; h < NH; h++) acc[h] = FINF;

    const char* rec = smem + (w * 128) * REC;
#pragma unroll 2
    for (int m = 0; m < 128; m++) {
        float4 q = *(const float4*)rec;
        ulonglong2 sA = *(const ulonglong2*)(rec + 16);
        ulonglong2 sBv = *(const ulonglong2*)(rec + 32);
        ulonglong2 sC = *(const ulonglong2*)(rec + 48);
        ulonglong2 sD = *(const ulonglong2*)(rec + 64);
        rec += REC;
        float dx = ax - q.x, dy = ay - q.y, dz = az - q.z;
        float dG = fmaf(dx, dx, fmaf(dy, dy, dz * dz));
        unsigned long long dG2 = pack2(dG, dG);
        unsigned long long e;
        float lo, hi;
        e = fma2(sn2[0], sA.x, dG2); unpack2(e, lo, hi);
        acc[0] = fminf(acc[0], lo);  acc[1] = fminf(acc[1], hi);
        e = fma2(sn2[1], sA.y, dG2); unpack2(e, lo, hi);
        acc[2] = fminf(acc[2], lo);  acc[3] = fminf(acc[3], hi);
        e = fma2(sn2[2], sBv.x, dG2); unpack2(e, lo, hi);
        acc[4] = fminf(acc[4], lo);  acc[5] = fminf(acc[5], hi);
        e = fma2(sn2[3], sBv.y, dG2); unpack2(e, lo, hi);
        acc[6] = fminf(acc[6], lo);  acc[7] = fminf(acc[7], hi);
        e = fma2(sn2[4], sC.x, dG2); unpack2(e, lo, hi);
        acc[8] = fminf(acc[8], lo);  acc[9] = fminf(acc[9], hi);
        e = fma2(sn2[5], sC.y, dG2); unpack2(e, lo, hi);
        acc[10] = fminf(acc[10], lo); acc[11] = fminf(acc[11], hi);
        e = fma2(sn2[6], sD.x, dG2); unpack2(e, lo, hi);
        acc[12] = fminf(acc[12], lo); acc[13] = fminf(acc[13], hi);
        e = fma2(sn2[7], sD.y, dG2); unpack2(e, lo, hi);
        acc[14] = fminf(acc[14], lo); acc[15] = fminf(acc[15], hi);
    }
    __syncthreads();    // tile no longer needed; reuse as exchange

    // Cross-warp (column-subset) exchange: ex[w][lane][h]
    float* ex = (float*)smem;
#pragma unroll
    for (int h = 0; h < NH; h++)
        ex[(w * 32 + lane) * NH + h] = acc[h];
    __syncthreads();

    // Combine subsets (min) + sum over the 32 rows; warp j handles h=j, j+8.
#pragma unroll
    for (int pass = 0; pass < 2; pass++) {
        int h = w + pass * 8;
        float mv = FINF;
#pragma unroll
        for (int w2 = 0; w2 < 8; w2++)
            mv = fminf(mv, ex[(w2 * 32 + lane) * NH + h]);
#pragma unroll
        for (int o = 16; o > 0; o >>= 1)
            mv += __shfl_down_sync(FULL, mv, o);
        if (lane == 0) g_bsum[bid * NH + h] = mv;
    }
    __threadfence();            // publish g_bsum before arrival
    __syncthreads();
    if (t == 0) {
        int old = atomicAdd(&g_cnt, 1);
        s_last = (old == NBLOCKS - 1);
        if (old == NBLOCKS - 1) g_cnt = 0;   // reset for next graph replay
    }
    __syncthreads();
    if (!s_last) return;

    // ---------------- finalize (last block; lanes 0..63) ----------------
    const int l = t;
    float v_nx = 0, v_ny = 0, v_nz = 0, v_px = 0, v_py = 0, v_pz = 0, v_cf = 0, v_sd = 0;
    int pos = l & 15, fb = l >> 4;

    if (l < 64) {
        int tv = thr_ptr[0];
        float tf = __int_as_float(tv);
        float thr = (tf >= 1e-6f && tf <= 1e9f) ? tf : (float)tv;

        const float* yq = ypred + l * 4;
        float qx = yq[0], qy = yq[1], qz = yq[2], qd = yq[3];
        float qi = 1.0f / sqrtf(qx * qx + qy * qy + qz * qz);
        v_nx = qx * qi; v_ny = qy * qi; v_nz = qz * qi;
        float qdh = qd * qi;
        v_px = -qdh * v_nx; v_py = -qdh * v_ny; v_pz = -qdh * v_nz;

        // sde = 2 * mean(row mins): sum this (b,h)'s 32 row-chunk partials
        volatile float* gb = g_bsum;
        float ssum = 0.0f;
        for (int r2 = 0; r2 < 32; r2++)
            ssum += gb[((fb * 32 + r2) * NH) + pos];
        v_sd = ssum * (2.0f / (float)NPTS);

        // group min/max over 16 lanes
        float mn = v_sd, mx = v_sd;
#pragma unroll
        for (int o = 8; o > 0; o >>= 1) {
            mn = fminf(mn, __shfl_xor_sync(FULL, mn, o, 16));
            mx = fmaxf(mx, __shfl_xor_sync(FULL, mx, o, 16));
        }
        v_cf = 1.0f - (v_sd - mn) / (mx - mn);

        // stable descending rank (== stable argsort(-cf))
        int rank = 0;
#pragma unroll
        for (int j = 0; j < NH; j++) {
            float cfj = __shfl_sync(FULL, v_cf, j, 16);
            rank += (cfj > v_cf) || (cfj == v_cf && j < pos);
        }
        int slot = fb * NH + rank;
        s_ex[0][slot] = v_nx; s_ex[1][slot] = v_ny; s_ex[2][slot] = v_nz;
        s_ex[3][slot] = v_px; s_ex[4][slot] = v_py; s_ex[5][slot] = v_pz;
        s_ex[6][slot] = v_cf; s_ex[7][slot] = v_sd;
        v_cf = thr;  // carry thr across the barrier
    }
    __syncthreads();
    if (l >= 64) return;

    float thr = v_cf;
    v_nx = s_ex[0][l]; v_ny = s_ex[1][l]; v_nz = s_ex[2][l];
    v_px = s_ex[3][l]; v_py = s_ex[4][l]; v_pz = s_ex[5][l];
    v_cf = s_ex[6][l]; v_sd = s_ex[7][l];

    // sequential NMS over sorted positions, live keep bits
    int keep = (v_sd <= thr);
#pragma unroll
    for (int i = 0; i < NH; i++) {
        int   ki  = __shfl_sync(FULL, keep, i, 16);
        float inx = __shfl_sync(FULL, v_nx, i, 16);
        float iny = __shfl_sync(FULL, v_ny, i, 16);
        float inz = __shfl_sync(FULL, v_nz, i, 16);
        float dt = inx * v_nx + iny * v_ny + inz * v_nz;
        if (ki && pos > i && dt > COS_THR) keep = 0;
    }

    // stable partition: kept first (in order), dropped after (in order)
    unsigned ball = __ballot_sync(FULL, keep);
    unsigned seg = (ball >> (l & 16)) & 0xFFFFu;
    int kept_before = __popc(seg & ((1u << pos) - 1));
    int total_kept  = __popc(seg);
    int dest = keep ? kept_before : total_kept + (pos - kept_before);

    float* o = out + (fb * NH + dest) * 8;
    float4 r0 = keep ? make_float4(v_nx, v_ny, v_nz, v_px) : make_float4(0, 0, 0, 0);
    float4 r1 = keep ? make_float4(v_py, v_pz, v_cf, v_sd) : make_float4(0, 0, 0, 0);
    ((float4*)o)[0] = r0;
    ((float4*)o)[1] = r1;
}

extern "C" void kernel_launch(void* const* d_in, const int* in_sizes, int n_in,
                              void* d_out, int out_size) {
    const float* pts = nullptr;    // 12288 elems
    const float* ypred = nullptr;  // 256 elems
    const int* thr = nullptr;      // 1 elem
    for (int i = 0; i < n_in; i++) {
        if (in_sizes[i] == NB * NPTS * 3)    pts   = (const float*)d_in[i];
        else if (in_sizes[i] == NB * NH * 4) ypred = (const float*)d_in[i];
        else if (in_sizes[i] == 1)           thr   = (const int*)d_in[i];
    }
    float* out = (float*)d_out;

    cudaFuncSetAttribute(plane_validator_kernel,
                         cudaFuncAttributeMaxDynamicSharedMemorySize, SMEM_BYTES);
    plane_validator_kernel<<<NBLOCKS, THREADS, SMEM_BYTES>>>(pts, ypred, thr, out);
}